// round 3
// baseline (speedup 1.0000x reference)
#include <cuda_runtime.h>
#include <cstdint>

#define H_DIM   4096
#define R_DIM   16
#define N_TOK   32768          // B*S
#define TB      4              // tokens per block
#define NTHREADS 256
#define KSCALE ((float)(2.0 / 0.95))
#define PDROP  0.05f

__device__ float g_mid[N_TOK * R_DIM];            // 2 MB scratch
__device__ float g_bt[8 * R_DIM * H_DIM];         // 2 MB: Bt[e][r][h]

// ---- packed f32x2 helpers (sm_103a) ---------------------------------------
__device__ __forceinline__ unsigned long long ffma2(unsigned long long a,
                                                    unsigned long long b,
                                                    unsigned long long c) {
    unsigned long long d;
    asm("fma.rn.f32x2 %0, %1, %2, %3;" : "=l"(d) : "l"(a), "l"(b), "l"(c));
    return d;
}
__device__ __forceinline__ unsigned long long pack2(float lo, float hi) {
    unsigned long long d;
    asm("mov.b64 %0, {%1, %2};" : "=l"(d) : "f"(lo), "f"(hi));
    return d;
}
__device__ __forceinline__ float2 unpack2(unsigned long long v) {
    float lo, hi;
    asm("mov.b64 {%0, %1}, %2;" : "=f"(lo), "=f"(hi) : "l"(v));
    return make_float2(lo, hi);
}

// ---------------------------------------------------------------------------
// Kernel 0: transpose lora_b[e][h][r] -> g_bt[e][r][h]  (2 MB, one-shot)
// Coalesced reads (r fastest), scattered 8B writes. ~5us.
// ---------------------------------------------------------------------------
__global__ void transpose_b_kernel(const float* __restrict__ lora_b)
{
    const int idx = blockIdx.x * blockDim.x + threadIdx.x;   // 524288 total
    const int r = idx & 15;
    const int h = (idx >> 4) & 4095;
    const int e = idx >> 16;
    g_bt[((size_t)e * R_DIM + r) * H_DIM + h] = lora_b[idx];
}

// ---------------------------------------------------------------------------
// Kernel 1: mid[g][r] = sum_h dropped(g,h) * A[e][r][h]
// TB=4 tokens per block, f32x2 packed accumulation over h-parity.
// ---------------------------------------------------------------------------
__global__ __launch_bounds__(NTHREADS, 2)
void lora_mid_kernel(const float* __restrict__ data,
                     const float* __restrict__ mask,
                     const float* __restrict__ lora_a)
{
    const int tid = threadIdx.x;
    const int g0  = blockIdx.x * TB;
    const int e   = g0 >> 12;
    const float* aBase = lora_a + (size_t)e * (R_DIM * H_DIM);

    unsigned long long acc2[TB][R_DIM];
#pragma unroll
    for (int t = 0; t < TB; t++)
#pragma unroll
        for (int r = 0; r < R_DIM; r++) acc2[t][r] = 0ull;

#pragma unroll
    for (int it = 0; it < H_DIM / (4 * NTHREADS); it++) {
        const int h4 = (it * NTHREADS + tid) * 4;

        unsigned long long drl[TB], drh[TB];
#pragma unroll
        for (int t = 0; t < TB; t++) {
            const size_t off = (size_t)(g0 + t) * H_DIM + h4;
            float4 x = *(const float4*)(data + off);
            float4 m = *(const float4*)(mask + off);
            float d0 = (m.x >= PDROP) ? x.x * KSCALE : 0.f;
            float d1 = (m.y >= PDROP) ? x.y * KSCALE : 0.f;
            float d2 = (m.z >= PDROP) ? x.z * KSCALE : 0.f;
            float d3 = (m.w >= PDROP) ? x.w * KSCALE : 0.f;
            drl[t] = pack2(d0, d1);
            drh[t] = pack2(d2, d3);
        }

#pragma unroll
        for (int r = 0; r < R_DIM; r++) {
            const float4 a4 = *(const float4*)(aBase + r * H_DIM + h4);
            const unsigned long long al = pack2(a4.x, a4.y);
            const unsigned long long ah = pack2(a4.z, a4.w);
#pragma unroll
            for (int t = 0; t < TB; t++) {
                acc2[t][r] = ffma2(drl[t], al, acc2[t][r]);
                acc2[t][r] = ffma2(drh[t], ah, acc2[t][r]);
            }
        }
    }

    // collapse f32x2 -> scalar, then butterfly reduce within warp
    float acc[TB][R_DIM];
#pragma unroll
    for (int t = 0; t < TB; t++)
#pragma unroll
        for (int r = 0; r < R_DIM; r++) {
            float2 p = unpack2(acc2[t][r]);
            float s = p.x + p.y;
#pragma unroll
            for (int off = 16; off > 0; off >>= 1)
                s += __shfl_xor_sync(0xffffffffu, s, off);
            acc[t][r] = s;
        }

    __shared__ float red[8][TB * R_DIM];
    const int wid  = tid >> 5;
    const int lane = tid & 31;
    if (lane == 0) {
#pragma unroll
        for (int t = 0; t < TB; t++)
#pragma unroll
            for (int r = 0; r < R_DIM; r++)
                red[wid][t * R_DIM + r] = acc[t][r];
    }
    __syncthreads();

    if (tid < TB * R_DIM) {
        float s = 0.f;
#pragma unroll
        for (int w = 0; w < 8; w++) s += red[w][tid];
        g_mid[(size_t)g0 * R_DIM + tid] = s;   // contiguous [t][r] layout
    }
}

// ---------------------------------------------------------------------------
// Kernel 2: out[g][h] = result[g][h] + sum_r mid[g][r] * Bt[e][r][h]
// grid = (N_TOK/TB, H/1024). Thread owns one float4 of h for TB=4 tokens.
// Bt loads are fully coalesced; mid lives in smem as duplicated f32x2 pairs.
// ---------------------------------------------------------------------------
__global__ __launch_bounds__(NTHREADS, 6)
void lora_out_kernel(const float* __restrict__ result,
                     float* __restrict__ out)
{
    const int tid = threadIdx.x;
    const int g0  = blockIdx.x * TB;
    const int e   = g0 >> 12;
    const int h4  = (blockIdx.y * NTHREADS + tid) * 4;
    const float* btBase = g_bt + (size_t)e * (R_DIM * H_DIM);

    // mid duplicated into f32x2 pairs in smem (LDS.64 broadcast)
    __shared__ float2 m2[TB * R_DIM];
    if (tid < TB * R_DIM) {
        float v = g_mid[(size_t)g0 * R_DIM + tid];
        m2[tid] = make_float2(v, v);
    }
    __syncthreads();
    const unsigned long long* m2u = (const unsigned long long*)m2;

    // init acc from result
    unsigned long long accl[TB], acch[TB];
#pragma unroll
    for (int t = 0; t < TB; t++) {
        float4 rv = *(const float4*)(result + (size_t)(g0 + t) * H_DIM + h4);
        accl[t] = pack2(rv.x, rv.y);
        acch[t] = pack2(rv.z, rv.w);
    }

#pragma unroll
    for (int r = 0; r < R_DIM; r++) {
        const float4 b4 = *(const float4*)(btBase + (size_t)r * H_DIM + h4);
        const unsigned long long bl = pack2(b4.x, b4.y);
        const unsigned long long bh = pack2(b4.z, b4.w);
#pragma unroll
        for (int t = 0; t < TB; t++) {
            const unsigned long long m = m2u[t * R_DIM + r];
            accl[t] = ffma2(m, bl, accl[t]);
            acch[t] = ffma2(m, bh, acch[t]);
        }
    }

#pragma unroll
    for (int t = 0; t < TB; t++) {
        float2 lo = unpack2(accl[t]);
        float2 hi = unpack2(acch[t]);
        *(float4*)(out + (size_t)(g0 + t) * H_DIM + h4) =
            make_float4(lo.x, lo.y, hi.x, hi.y);
    }
}

// ---------------------------------------------------------------------------
extern "C" void kernel_launch(void* const* d_in, const int* in_sizes, int n_in,
                              void* d_out, int out_size)
{
    const float* result   = (const float*)d_in[0];
    const float* data     = (const float*)d_in[1];
    const float* dropmask = (const float*)d_in[2];
    const float* lora_a   = (const float*)d_in[3];
    const float* lora_b   = (const float*)d_in[4];
    float* out = (float*)d_out;

    transpose_b_kernel<<<(8 * R_DIM * H_DIM) / NTHREADS, NTHREADS>>>(lora_b);
    lora_mid_kernel<<<N_TOK / TB, NTHREADS>>>(data, dropmask, lora_a);

    dim3 grid2(N_TOK / TB, H_DIM / (4 * NTHREADS));
    lora_out_kernel<<<grid2, NTHREADS>>>(result, out);
}

// round 4
// speedup vs baseline: 2.0875x; 2.0875x over previous
#include <cuda_runtime.h>
#include <cstdint>

#define H_DIM   4096
#define R_DIM   16
#define N_TOK   32768          // B*S
#define TB      4              // tokens per block (kernel1)
#define TB2     8              // tokens per block (kernel2)
#define NTHREADS 256
#define KSCALE ((float)(2.0 / 0.95))
#define PDROP  0.05f

__device__ float g_mid[N_TOK * R_DIM];        // 2 MB scratch
__device__ float g_bt[8 * R_DIM * H_DIM];     // 2 MB: Bt[e][r][h]

// ---------------------------------------------------------------------------
// Kernel 0: transpose lora_b[e][h][r] -> g_bt[e][r][h]  (~6us, one-shot)
// ---------------------------------------------------------------------------
__global__ void transpose_b_kernel(const float* __restrict__ lora_b)
{
    const int idx = blockIdx.x * blockDim.x + threadIdx.x;   // 524288 total
    const int r = idx & 15;
    const int h = (idx >> 4) & 4095;
    const int e = idx >> 16;
    g_bt[((size_t)e * R_DIM + r) * H_DIM + h] = lora_b[idx];
}

// ---------------------------------------------------------------------------
// Kernel 1: mid[g][r] = sum_h dropped(g,h) * A[e][r][h]
// R1-proven structure: scalar FFMA, 64 f32 accumulators, TB=4.
// data/mask use .cs streaming loads (zero reuse) so L1 keeps A rows resident.
// ---------------------------------------------------------------------------
__global__ __launch_bounds__(NTHREADS, 2)
void lora_mid_kernel(const float* __restrict__ data,
                     const float* __restrict__ mask,
                     const float* __restrict__ lora_a)
{
    const int tid = threadIdx.x;
    const int g0  = blockIdx.x * TB;
    const int e   = g0 >> 12;
    const float* aBase = lora_a + (size_t)e * (R_DIM * H_DIM);

    float acc[TB][R_DIM];
#pragma unroll
    for (int t = 0; t < TB; t++)
#pragma unroll
        for (int r = 0; r < R_DIM; r++) acc[t][r] = 0.f;

#pragma unroll
    for (int it = 0; it < H_DIM / (4 * NTHREADS); it++) {
        const int h4 = (it * NTHREADS + tid) * 4;

        float4 dr[TB];
#pragma unroll
        for (int t = 0; t < TB; t++) {
            const size_t off = (size_t)(g0 + t) * H_DIM + h4;
            float4 x = __ldcs((const float4*)(data + off));
            float4 m = __ldcs((const float4*)(mask + off));
            dr[t].x = (m.x >= PDROP) ? x.x * KSCALE : 0.f;
            dr[t].y = (m.y >= PDROP) ? x.y * KSCALE : 0.f;
            dr[t].z = (m.z >= PDROP) ? x.z * KSCALE : 0.f;
            dr[t].w = (m.w >= PDROP) ? x.w * KSCALE : 0.f;
        }

#pragma unroll
        for (int r = 0; r < R_DIM; r++) {
            const float4 a4 = *(const float4*)(aBase + r * H_DIM + h4);
#pragma unroll
            for (int t = 0; t < TB; t++) {
                acc[t][r] += dr[t].x * a4.x + dr[t].y * a4.y
                           + dr[t].z * a4.z + dr[t].w * a4.w;
            }
        }
    }

    // Intra-warp butterfly reduction
#pragma unroll
    for (int t = 0; t < TB; t++)
#pragma unroll
        for (int r = 0; r < R_DIM; r++) {
#pragma unroll
            for (int off = 16; off > 0; off >>= 1)
                acc[t][r] += __shfl_xor_sync(0xffffffffu, acc[t][r], off);
        }

    // Cross-warp via smem
    __shared__ float red[8][TB * R_DIM];
    const int wid  = tid >> 5;
    const int lane = tid & 31;
    if (lane == 0) {
#pragma unroll
        for (int t = 0; t < TB; t++)
#pragma unroll
            for (int r = 0; r < R_DIM; r++)
                red[wid][t * R_DIM + r] = acc[t][r];
    }
    __syncthreads();

    if (tid < TB * R_DIM) {
        float s = 0.f;
#pragma unroll
        for (int w = 0; w < 8; w++) s += red[w][tid];
        g_mid[(size_t)g0 * R_DIM + tid] = s;   // contiguous [t][r]
    }
}

// ---------------------------------------------------------------------------
// Kernel 2: out[g][h] = result[g][h] + sum_r mid[g][r] * Bt[e][r][h]
// TB2=8 tokens/block; Bt float4 loads fully coalesced & reused across 8
// tokens; mid in smem (LDS broadcast); float4 streaming result/out.
// grid = (N_TOK/TB2, H/1024)
// ---------------------------------------------------------------------------
__global__ __launch_bounds__(NTHREADS)
void lora_out_kernel(const float* __restrict__ result,
                     float* __restrict__ out)
{
    const int tid = threadIdx.x;
    const int g0  = blockIdx.x * TB2;
    const int e   = g0 >> 12;
    const int h4  = (blockIdx.y * NTHREADS + tid) * 4;
    const float* btBase = g_bt + (size_t)e * (R_DIM * H_DIM);

    __shared__ float smid[TB2 * R_DIM];
    if (tid < TB2 * R_DIM)
        smid[tid] = g_mid[(size_t)g0 * R_DIM + tid];
    __syncthreads();

    float4 acc[TB2];
#pragma unroll
    for (int t = 0; t < TB2; t++)
        acc[t] = __ldcs((const float4*)(result + (size_t)(g0 + t) * H_DIM + h4));

#pragma unroll
    for (int r = 0; r < R_DIM; r++) {
        const float4 b4 = *(const float4*)(btBase + (size_t)r * H_DIM + h4);
#pragma unroll
        for (int t = 0; t < TB2; t++) {
            const float m = smid[t * R_DIM + r];
            acc[t].x += m * b4.x;
            acc[t].y += m * b4.y;
            acc[t].z += m * b4.z;
            acc[t].w += m * b4.w;
        }
    }

#pragma unroll
    for (int t = 0; t < TB2; t++)
        __stcs((float4*)(out + (size_t)(g0 + t) * H_DIM + h4), acc[t]);
}

// ---------------------------------------------------------------------------
extern "C" void kernel_launch(void* const* d_in, const int* in_sizes, int n_in,
                              void* d_out, int out_size)
{
    const float* result   = (const float*)d_in[0];
    const float* data     = (const float*)d_in[1];
    const float* dropmask = (const float*)d_in[2];
    const float* lora_a   = (const float*)d_in[3];
    const float* lora_b   = (const float*)d_in[4];
    float* out = (float*)d_out;

    transpose_b_kernel<<<(8 * R_DIM * H_DIM) / NTHREADS, NTHREADS>>>(lora_b);
    lora_mid_kernel<<<N_TOK / TB, NTHREADS>>>(data, dropmask, lora_a);

    dim3 grid2(N_TOK / TB2, H_DIM / (4 * NTHREADS));
    lora_out_kernel<<<grid2, NTHREADS>>>(result, out);
}